// round 16
// baseline (speedup 1.0000x reference)
#include <cuda_runtime.h>
#include <cuda_fp16.h>

#define BB 4
#define MM 128
#define LL 512
#define DD 768

#define LSPLIT 6
#define LMAX   86
#define APADU  68           // u32 row stride for sh_a (64 m + pad, 16B-aligned)
#define NEGH   0xFC00FC00u  // fp16x2 (-inf,-inf)
#define NDB    (DD / 128)   // 6 d-tiles

#define NPROD  (NDB * LSPLIT * 2 * BB)   // 288 producer blocks
#define NGRP   (BB * NDB * 2)            // 48 combiner groups (b, dblk, mhalf)

// fp16 partials [sp][b][m][d] = 4.7 MB static scratch (no allocs)
__device__ unsigned short g_scratch[LSPLIT * BB * MM * DD];
// per-(b,dblk,mhalf) arrival counters; combiner resets -> graph-replay safe
__device__ int g_cnt[NGRP];

#define SH_H_U32   (LMAX * 64)
#define SMEM_BYTES ((SH_H_U32 + LMAX * APADU) * (int)sizeof(unsigned int))  // ~45.4 KB
#define SP_STRIDE_U4 (BB * MM * DD / 8)   // uint4 units per sp-partial

__global__ __launch_bounds__(256)
void mr_fused(const float* __restrict__ h, const int* __restrict__ mask,
              float* __restrict__ out)
{
    const int bid = blockIdx.x;
    const int tid = threadIdx.x;

    if (bid < NPROD) {
        // ================= producer (byte-identical work to R14 mr_main) ==========
        extern __shared__ unsigned int sm[];
        unsigned int* sh_h = sm;              // [l][64] fp16x2 (128 d)
        unsigned int* sh_a = sm + SH_H_U32;   // [l][APADU] additive splat

        const int dblk = bid % NDB;
        const int rest = bid / NDB;           // 0..47
        const int yy   = rest % (LSPLIT * 2);
        const int b    = rest / (LSPLIT * 2);
        const int sp   = yy >> 1;
        const int mh   = yy & 1;
        const int d0   = dblk * 128;
        const int m0   = mh * 64;
        const int l0   = sp * 85 + (sp < 2 ? sp : 2);
        const int llen = 85 + (sp < 2 ? 1 : 0);

        const int lane = tid & 31;
        const int w    = tid >> 5;            // 8 warps; warp w -> m rows [m0+8w, ..+8)

        // ---- stage h tile: coalesced float4 LDG -> fp16x2 -> STS ----
        {
            const float4* hg = (const float4*)h + ((size_t)b * LL + l0) * (DD / 4) + (d0 >> 2);
            const int n = llen * 32;
            for (int idx = tid; idx < n; idx += 256) {
                const int l = idx >> 5, q = idx & 31;
                const float4 v = hg[(size_t)l * (DD / 4) + q];
                const half2 p0 = __float22half2_rn(make_float2(v.x, v.y));
                const half2 p1 = __float22half2_rn(make_float2(v.z, v.w));
                uint2 o; o.x = *(const unsigned int*)&p0; o.y = *(const unsigned int*)&p1;
                *(uint2*)&sh_h[l * 64 + q * 2] = o;
            }
        }
        // ---- stage mask transposed [l][m] (64 m); LDG coalesced over l ----
        for (int m = w; m < 64; m += 8) {
            const int* mg = mask + ((size_t)b * MM + m0 + m) * LL + l0;
            for (int lb = lane; lb < llen; lb += 32)
                sh_a[lb * APADU + m] = mg[lb] ? 0u : NEGH;
        }
        __syncthreads();

        // ---- accumulate: 8 m x 128 d (fp16x2) per warp; 2 l per iter ----
        const unsigned int ninf = NEGH;
        const half2 hninf = *(const half2*)&ninf;
        half2 acc[8][2];
#pragma unroll
        for (int i = 0; i < 8; ++i) { acc[i][0] = hninf; acc[i][1] = hninf; }

        const int mb = w * 8;
        int l = 0;
        for (; l + 2 <= llen; l += 2) {
            const uint2 hva = *(const uint2*)&sh_h[(l + 0) * 64 + lane * 2];
            const uint2 hvb = *(const uint2*)&sh_h[(l + 1) * 64 + lane * 2];
            const uint4 a0  = *(const uint4*)&sh_a[(l + 0) * APADU + mb];
            const uint4 a1  = *(const uint4*)&sh_a[(l + 0) * APADU + mb + 4];
            const uint4 b0  = *(const uint4*)&sh_a[(l + 1) * APADU + mb];
            const uint4 b1  = *(const uint4*)&sh_a[(l + 1) * APADU + mb + 4];

            const half2 ha0 = *(const half2*)&hva.x, ha1 = *(const half2*)&hva.y;
            const half2 hb0 = *(const half2*)&hvb.x, hb1 = *(const half2*)&hvb.y;
            const unsigned int av[8] = {a0.x,a0.y,a0.z,a0.w, a1.x,a1.y,a1.z,a1.w};
            const unsigned int bv[8] = {b0.x,b0.y,b0.z,b0.w, b1.x,b1.y,b1.z,b1.w};
#pragma unroll
            for (int i = 0; i < 8; ++i) {
                const half2 aa = *(const half2*)&av[i];
                const half2 ab = *(const half2*)&bv[i];
                acc[i][0] = __hmax2(__hmax2(acc[i][0], __hadd2(ha0, aa)), __hadd2(hb0, ab));
                acc[i][1] = __hmax2(__hmax2(acc[i][1], __hadd2(ha1, aa)), __hadd2(hb1, ab));
            }
        }
        if (l < llen) {
            const uint2 hv = *(const uint2*)&sh_h[l * 64 + lane * 2];
            const uint4 a0 = *(const uint4*)&sh_a[l * APADU + mb];
            const uint4 a1 = *(const uint4*)&sh_a[l * APADU + mb + 4];
            const half2 h0 = *(const half2*)&hv.x, h1 = *(const half2*)&hv.y;
            const unsigned int av[8] = {a0.x,a0.y,a0.z,a0.w, a1.x,a1.y,a1.z,a1.w};
#pragma unroll
            for (int i = 0; i < 8; ++i) {
                const half2 a = *(const half2*)&av[i];
                acc[i][0] = __hmax2(acc[i][0], __hadd2(h0, a));
                acc[i][1] = __hmax2(acc[i][1], __hadd2(h1, a));
            }
        }

        // ---- write fp16 partials, then release-signal the group counter ----
        unsigned short* op = g_scratch + (((size_t)sp * BB + b) * MM + m0 + mb) * DD + d0 + lane * 4;
#pragma unroll
        for (int i = 0; i < 8; ++i) {
            uint2 o;
            o.x = *(const unsigned int*)&acc[i][0];
            o.y = *(const unsigned int*)&acc[i][1];
            *(uint2*)(op + (size_t)i * DD) = o;
        }
        __threadfence();          // release: partials visible before count
        __syncthreads();          // all warps' stores issued
        if (tid == 0)
            atomicAdd(&g_cnt[(b * NDB + dblk) * 2 + mh], 1);

    } else {
        // ================= combiner: one block per (b, dblk, mhalf) ==============
        const int c    = bid - NPROD;          // 0..47
        const int b    = c / (NDB * 2);
        const int dblk = (c / 2) % NDB;
        const int mh   = c & 1;
        const int d0   = dblk * 128;
        const int m0   = mh * 64;

        // spin until all 6 L-split producers of this group arrived
        if (tid == 0) {
            while (atomicAdd(&g_cnt[c], 0) < LSPLIT) { }
            g_cnt[c] = 0;                      // reset for next graph replay
        }
        __syncthreads();
        __threadfence();                        // acquire: partials now readable

        // 64 m x 128 d = 1024 uint4 per sp; 4 per thread, 6-way MLP
        const uint4* s = (const uint4*)g_scratch;
#pragma unroll
        for (int k = 0; k < 4; ++k) {
            const int e = k * 256 + tid;        // 0..1023
            const int m = e >> 4, q = e & 15;   // 16 uint4 per m-row
            const size_t base = (((size_t)b * MM + m0 + m) * DD + d0) / 8 + q;

            uint4 v[LSPLIT];
#pragma unroll
            for (int sp = 0; sp < LSPLIT; ++sp)
                v[sp] = s[(size_t)sp * SP_STRIDE_U4 + base];

            half2 r0 = *(const half2*)&v[0].x;
            half2 r1 = *(const half2*)&v[0].y;
            half2 r2 = *(const half2*)&v[0].z;
            half2 r3 = *(const half2*)&v[0].w;
#pragma unroll
            for (int sp = 1; sp < LSPLIT; ++sp) {
                r0 = __hmax2(r0, *(const half2*)&v[sp].x);
                r1 = __hmax2(r1, *(const half2*)&v[sp].y);
                r2 = __hmax2(r2, *(const half2*)&v[sp].z);
                r3 = __hmax2(r3, *(const half2*)&v[sp].w);
            }
            const float2 f0 = __half22float2(r0);
            const float2 f1 = __half22float2(r1);
            const float2 f2 = __half22float2(r2);
            const float2 f3 = __half22float2(r3);
            float4 o0, o1;
            o0.x = f0.x; o0.y = f0.y; o0.z = f1.x; o0.w = f1.y;
            o1.x = f2.x; o1.y = f2.y; o1.z = f3.x; o1.w = f3.y;
            float4* og = (float4*)out + base * 2;
            og[0] = o0;
            og[1] = o1;
        }
    }
}

extern "C" void kernel_launch(void* const* d_in, const int* in_sizes, int n_in,
                              void* d_out, int out_size)
{
    const float* h    = (const float*)d_in[0];
    const int*   mask = (const int*)  d_in[1];
    float*       out  = (float*)d_out;

    cudaFuncSetAttribute(mr_fused,
                         cudaFuncAttributeMaxDynamicSharedMemorySize, SMEM_BYTES);

    // 288 producers (bids 0-287, resident in wave 1) + 48 spin-combiners
    mr_fused<<<NPROD + NGRP, 256, SMEM_BYTES>>>(h, mask, out);
}

// round 17
// speedup vs baseline: 1.0014x; 1.0014x over previous
#include <cuda_runtime.h>
#include <cuda_fp16.h>

#define BB 4
#define MM 128
#define LL 512
#define DD 768

#define LSPLIT 6
#define LMAX   86
#define APADU  68           // u32 row stride for sh_a (64 m + pad, 16B-aligned)
#define NEGH   0xFC00FC00u  // fp16x2 (-inf,-inf)

// keyed-max accumulator [B][M][D] ints, zero-init (= key(+0.0)); convert restores
__device__ int g_keys[BB * MM * DD];

#define SH_H_U32   (LMAX * 64)
#define SMEM_BYTES ((SH_H_U32 + LMAX * APADU) * (int)sizeof(unsigned int))  // ~45.4 KB

// order-preserving float<->int key (involution)
__device__ __forceinline__ int fkey(float f)
{
    const int i = __float_as_int(f);
    return i >= 0 ? i : (i ^ 0x7FFFFFFF);
}

__global__ __launch_bounds__(256)
void mr_main(const float* __restrict__ h, const int* __restrict__ mask)
{
    extern __shared__ unsigned int sm[];
    unsigned int* sh_h = sm;              // [l][64] fp16x2 (128 d)
    unsigned int* sh_a = sm + SH_H_U32;   // [l][APADU] additive splat (0 or -inf,-inf)

    const int b    = blockIdx.z;
    const int d0   = blockIdx.x * 128;
    const int sp   = blockIdx.y >> 1;
    const int m0   = (blockIdx.y & 1) * 64;            // m-half
    const int l0   = sp * 85 + (sp < 2 ? sp : 2);
    const int llen = 85 + (sp < 2 ? 1 : 0);

    const int tid  = threadIdx.x;
    const int lane = tid & 31;
    const int w    = tid >> 5;            // 8 warps; warp w -> m rows [m0+8w, m0+8w+8)

    // ---- stage h tile: coalesced float4 LDG -> fp16x2 -> STS ----
    {
        const float4* hg = (const float4*)h + ((size_t)b * LL + l0) * (DD / 4) + (d0 >> 2);
        const int n = llen * 32;
        for (int idx = tid; idx < n; idx += 256) {
            const int l = idx >> 5, q = idx & 31;
            const float4 v = hg[(size_t)l * (DD / 4) + q];
            const half2 p0 = __float22half2_rn(make_float2(v.x, v.y));
            const half2 p1 = __float22half2_rn(make_float2(v.z, v.w));
            uint2 o; o.x = *(const unsigned int*)&p0; o.y = *(const unsigned int*)&p1;
            *(uint2*)&sh_h[l * 64 + q * 2] = o;
        }
    }
    // ---- stage mask transposed [l][m] (64 m); LDG coalesced over l ----
    for (int m = w; m < 64; m += 8) {
        const int* mg = mask + ((size_t)b * MM + m0 + m) * LL + l0;
        for (int lb = lane; lb < llen; lb += 32)
            sh_a[lb * APADU + m] = mg[lb] ? 0u : NEGH;
    }
    __syncthreads();

    // ---- accumulate: 8 m x 128 d (fp16x2) per warp; 2 l per iter, loads batched ----
    const unsigned int ninf = NEGH;
    const half2 hninf = *(const half2*)&ninf;
    half2 acc[8][2];
#pragma unroll
    for (int i = 0; i < 8; ++i) { acc[i][0] = hninf; acc[i][1] = hninf; }

    const int mb = w * 8;
    int l = 0;
    for (; l + 2 <= llen; l += 2) {
        // 6 independent LDS up-front
        const uint2 hva = *(const uint2*)&sh_h[(l + 0) * 64 + lane * 2];
        const uint2 hvb = *(const uint2*)&sh_h[(l + 1) * 64 + lane * 2];
        const uint4 a0  = *(const uint4*)&sh_a[(l + 0) * APADU + mb];
        const uint4 a1  = *(const uint4*)&sh_a[(l + 0) * APADU + mb + 4];
        const uint4 b0  = *(const uint4*)&sh_a[(l + 1) * APADU + mb];
        const uint4 b1  = *(const uint4*)&sh_a[(l + 1) * APADU + mb + 4];

        const half2 ha0 = *(const half2*)&hva.x, ha1 = *(const half2*)&hva.y;
        const half2 hb0 = *(const half2*)&hvb.x, hb1 = *(const half2*)&hvb.y;
        const unsigned int av[8] = {a0.x,a0.y,a0.z,a0.w, a1.x,a1.y,a1.z,a1.w};
        const unsigned int bv[8] = {b0.x,b0.y,b0.z,b0.w, b1.x,b1.y,b1.z,b1.w};
#pragma unroll
        for (int i = 0; i < 8; ++i) {
            const half2 aa = *(const half2*)&av[i];
            const half2 ab = *(const half2*)&bv[i];
            acc[i][0] = __hmax2(__hmax2(acc[i][0], __hadd2(ha0, aa)), __hadd2(hb0, ab));
            acc[i][1] = __hmax2(__hmax2(acc[i][1], __hadd2(ha1, aa)), __hadd2(hb1, ab));
        }
    }
    if (l < llen) {   // tail (llen odd: 85)
        const uint2 hv = *(const uint2*)&sh_h[l * 64 + lane * 2];
        const uint4 a0 = *(const uint4*)&sh_a[l * APADU + mb];
        const uint4 a1 = *(const uint4*)&sh_a[l * APADU + mb + 4];
        const half2 h0 = *(const half2*)&hv.x, h1 = *(const half2*)&hv.y;
        const unsigned int av[8] = {a0.x,a0.y,a0.z,a0.w, a1.x,a1.y,a1.z,a1.w};
#pragma unroll
        for (int i = 0; i < 8; ++i) {
            const half2 a = *(const half2*)&av[i];
            acc[i][0] = __hmax2(acc[i][0], __hadd2(h0, a));
            acc[i][1] = __hmax2(acc[i][1], __hadd2(h1, a));
        }
    }

    // ---- epilogue: keyed atomicMax straight into g_keys (no partials) ----
#pragma unroll
    for (int i = 0; i < 8; ++i) {
        const float2 fa = __half22float2(acc[i][0]);
        const float2 fb = __half22float2(acc[i][1]);
        int* op = g_keys + ((size_t)((b * MM) + m0 + mb + i) * DD + d0 + lane * 4);
        atomicMax(op + 0, fkey(fa.x));
        atomicMax(op + 1, fkey(fa.y));
        atomicMax(op + 2, fkey(fb.x));
        atomicMax(op + 3, fkey(fb.y));
    }
}

#define TOTI4 (BB * MM * DD / 4)    // 98304 int4

__global__ __launch_bounds__(256, 1)
void mr_convert(float* __restrict__ out)
{
    const int t = blockIdx.x * 256 + threadIdx.x;    // 0..98303
    int4* kp = (int4*)g_keys + t;
    const int4 k = *kp;

    uint4 o;
    o.x = (unsigned int)fkey(__int_as_float(k.x) * 0.0f == 0.0f ? 0.0f : 0.0f); // placeholder avoided below
    // unkey (fkey is an involution on the int domain)
    int4 u;
    u.x = k.x >= 0 ? k.x : (k.x ^ 0x7FFFFFFF);
    u.y = k.y >= 0 ? k.y : (k.y ^ 0x7FFFFFFF);
    u.z = k.z >= 0 ? k.z : (k.z ^ 0x7FFFFFFF);
    u.w = k.w >= 0 ? k.w : (k.w ^ 0x7FFFFFFF);

    ((int4*)out)[t] = u;                 // raw fp32 bits

    const int4 z = make_int4(0, 0, 0, 0);
    *kp = z;                             // restore identity for next replay
}

extern "C" void kernel_launch(void* const* d_in, const int* in_sizes, int n_in,
                              void* d_out, int out_size)
{
    const float* h    = (const float*)d_in[0];
    const int*   mask = (const int*)  d_in[1];
    float*       out  = (float*)d_out;

    cudaFuncSetAttribute(mr_main,
                         cudaFuncAttributeMaxDynamicSharedMemorySize, SMEM_BYTES);

    dim3 grid(DD / 128, LSPLIT * 2, BB);   // 6 x 12 x 4 = 288 blocks, occ 2
    mr_main<<<grid, 256, SMEM_BYTES>>>(h, mask);
    mr_convert<<<TOTI4 / 256, 256>>>(out);    // 384 blocks, 1.5MB r/w + restore
}